// round 17
// baseline (speedup 1.0000x reference)
#include <cuda_runtime.h>

// SPNBP compute_quant_to_alphabet — WARP-PER-N: each warp owns one n
// end-to-end (constants, scatter, reduce, store). No block barriers at all.
//
// out[n,b] = T[b+1] - T[b],  T[j] = sum_k w_k * e_j^k,
//   e_0 = 0, e_256 = 1, e_j = Phi(basec_k + (j-128)*inv_k) (increasing in j).
//
// Phi (A&S 26.2.17, pdf constant folded, MUFU-only rcp) saturates EXACTLY in
// fp32 at |x| >= 5.5. Decompose T = A + prefix(m):
//   A[j]    += w_k * Phi(cc_j)  for active edges j in [jlo_k, jsat_k) (<= ~22)
//   m[jsat] += w_k              (Phi == 1 for all j >= jsat)
// prefix cancels in the diff: out[b] = A[b+1] - A[b] + m[b+1].
//
// Block = 256 thr = 8 warps = 8 n's; grid = N/8 = 128 (<= 1 block/SM).
// Per warp: lanes 0-31 each set up 2 k's (64 total), then 64 unrolled
// scatter passes alternating between TWO accumulator arrays (halves the
// LDS->FADD->STS alias chain), then an 8-step diff + coalesced store.
// Warps are fully independent: __syncwarp only.

#define NBINS 256
#define KMAX  64
#define NW    8                    // warps (= n's) per block
#define TPB   (NW * 32)
#define ASZ   260                  // per-array stride (256+pad)

__device__ __forceinline__ float rcp_approx(float x)
{
    float r;
    asm("rcp.approx.f32 %0, %1;" : "=f"(r) : "f"(x));
    return r;
}

__device__ __forceinline__ float phi_fast(float x)
{
    const float ax = fabsf(x);
    const float t  = rcp_approx(fmaf(0.2316419f, ax, 1.0f));   // MUFU.RCP only
    // A&S 26.2.17 coefficients pre-scaled by 1/sqrt(2*pi)
    float p = fmaf(0.53070271f, t, -0.72657598f);
    p = fmaf(p, t,  0.71070688f);
    p = fmaf(p, t, -0.14224835f);
    p = fmaf(p, t,  0.12741479f);
    p = p * t;
    const float e = exp2f(-0.72134752f * x * x);     // log2(e)/2 folded
    const float y = fmaf(-e, p, 1.0f);               // Phi(|x|); ==1 for ax>=5.5
    return (x >= 0.0f) ? y : (1.0f - y);
}

__global__ __launch_bounds__(TPB)
void spnbp_kernel(const float* __restrict__ Q,
                  const float* __restrict__ Q0,
                  const float* __restrict__ base_mean,
                  const float* __restrict__ base_var,
                  const float* __restrict__ mix_p,
                  float* __restrict__ out,
                  int N, int K)
{
    const int warp = threadIdx.x >> 5;
    const int lane = threadIdx.x & 31;
    const int n    = blockIdx.x * NW + warp;          // this warp's n

    __shared__ alignas(16) float  s_A[NW][2][ASZ];    // 2 accumulators / warp
    __shared__ alignas(16) float  s_M[NW][ASZ];       // markers / warp
    __shared__ alignas(16) float4 s_kc[NW][KMAX];     // per-k constants / warp

    if (n < N) {
        // ---- zero this warp's arrays ----
        {
            float4* zA = (float4*)&s_A[warp][0][0];   // 2*ASZ/4 = 130 float4
            float4* zM = (float4*)&s_M[warp][0];      //   ASZ/4 =  65 float4
            #pragma unroll
            for (int i = lane; i < 2 * ASZ / 4; i += 32)
                zA[i] = make_float4(0.f, 0.f, 0.f, 0.f);
            #pragma unroll
            for (int i = lane; i < ASZ / 4 + 1; i += 32)
                if (i < ASZ / 4) zM[i] = make_float4(0.f, 0.f, 0.f, 0.f);
        }
        __syncwarp();

        // ---- each lane sets up 2 k's: k = lane and k = lane + 32 ----
        const float qd = Q[(size_t)n * N + n];        // diag(Q)[n] (broadcast)
        const float q0 = Q0[n];
        #pragma unroll
        for (int h = 0; h < 2; ++h) {
            const int k = lane + (h << 5);
            float basec2 = 0.0f, inv = 1.0f, w = 0.0f;
            int   jlo = 1, jsat = 1;
            if (k < K) {
                const float bm = base_mean[k * N + n];
                const float bv = base_var [k * N + n];
                w   = mix_p[k * N + n];
                inv = rsqrtf(qd * qd * bv);
                const float basec = (-qd * bm - q0) * inv;
                const float rinv  = rcp_approx(inv);
                // cc crosses -5.5 at tlo, +5.5 at thi (cc increasing in j)
                const float tlo = fmaf(-5.5f - basec, rinv, 128.0f);
                const float thi = fmaf( 5.5f - basec, rinv, 128.0f);
                // j < jlo: Phi exact 0 (incl. forced e_0);
                // j >= jsat: Phi exact 1 (incl. forced e_256)
                jlo  = __float2int_rd(fminf(fmaxf(tlo, 1.0f), 256.0f));
                jsat = __float2int_ru(fminf(fmaxf(thi, 0.0f), 256.0f));
                if (jsat < jlo) jsat = jlo;
                // pre-shift: cc at edge (jlo+i) = fma(i, inv, basec2)
                basec2 = fmaf((float)(jlo - 128), inv, basec);
            }
            s_kc[warp][k] = make_float4(basec2, inv, w,
                                        __int_as_float(jlo | ((jsat - jlo) << 16)));
            atomicAdd(&s_M[warp][jsat], w);           // step mass at jsat
        }
        __syncwarp();

        // ---- 64 scatter passes, alternating accumulators (chain /2) ----
        {
            float* __restrict__ acc0 = &s_A[warp][0][0];
            float* __restrict__ acc1 = &s_A[warp][1][0];
            const float lanef = (float)lane;
            #pragma unroll 8
            for (int p = 0; p < KMAX; ++p) {
                const float4 c   = s_kc[warp][p];       // LDS.128 broadcast
                const int    pk  = __float_as_int(c.w);
                const int    jlo = pk & 0xffff;
                const int    nE  = pk >> 16;            // <= ~22 here
                float* __restrict__ acc = (p & 1) ? acc1 : acc0;
                if (lane < nE) {
                    const float cc = fmaf(lanef, c.y, c.x);
                    acc[jlo + lane] += c.z * phi_fast(cc);  // conflict-free RMW
                }
                if (nE > 32) {                          // cold, never taken here
                    for (int i = 32 + lane; i < nE; i += 32) {
                        const float cc = fmaf((float)i, c.y, c.x);
                        acc[jlo + i] += c.z * phi_fast(cc);
                    }
                }
            }
        }
        __syncwarp();

        // ---- per-warp reduce + diff + coalesced store ----
        {
            float* __restrict__ A0 = &s_A[warp][0][0];
            float* __restrict__ A1 = &s_A[warp][1][0];
            float* __restrict__ M  = &s_M[warp][0];
            #pragma unroll
            for (int j = 0; j < NBINS / 32; ++j) {
                const int b = (j << 5) + lane;
                const float d = A0[b + 1] - A0[b]       // A[0]=A[256]=0 by constr.
                              + A1[b + 1] - A1[b]
                              + M[b + 1];
                out[(size_t)n * NBINS + b] = d;
            }
        }
    }
}

extern "C" void kernel_launch(void* const* d_in, const int* in_sizes, int n_in,
                              void* d_out, int out_size)
{
    const float* Q     = (const float*)d_in[0];   // [N, N]
    const float* Q0    = (const float*)d_in[1];   // [N, 1]
    const float* bmean = (const float*)d_in[2];   // [K, N]
    const float* bvar  = (const float*)d_in[3];   // [K, N]
    const float* mp    = (const float*)d_in[4];   // [K, N, 1]
    float* out = (float*)d_out;                   // [N, 256]

    const int N = in_sizes[1];                    // 1024
    const int K = in_sizes[2] / N;                // 64

    spnbp_kernel<<<(N + NW - 1) / NW, TPB>>>(Q, Q0, bmean, bvar, mp, out, N, K);
}